// round 3
// baseline (speedup 1.0000x reference)
#include <cuda_runtime.h>
#include <cstdint>

#define N_NODES 50000
#define N_EDGES 800000
#define HID 64
#define N_GRAPHS 256
#define BN_EPS 1e-5f

// ---------------- scratch (static device globals; no runtime allocation) ----
__device__ float g_t[(size_t)N_NODES * HID];   // t = h + agg(h) (GEMM input)
__device__ float g_z[(size_t)N_NODES * HID];   // z = relu?( t @ W + b ) (pre-BN)
__device__ int   g_deg[N_NODES];
__device__ int   g_rowptr[N_NODES + 1];
__device__ int   g_cursor[N_NODES];
__device__ int2  g_csr[N_EDGES];               // {src, weight-bits}
__device__ float g_stats[3 * 128];             // per layer: [sum(64) | sumsq(64)]
__device__ float g_pooled[N_GRAPHS * HID];
__device__ int   g_bsums[64];

// ---------------- init: zero histogram, pooled, stats ----------------------
__global__ void k_init() {
    int i = blockIdx.x * 256 + threadIdx.x;
    if (i < N_NODES) g_deg[i] = 0;
    if (i < N_GRAPHS * HID) g_pooled[i] = 0.0f;
    if (i < 3 * 128) g_stats[i] = 0.0f;
}

// ---------------- CSR build (edge_index is int32 on device!) ----------------
__global__ void k_count(const int* __restrict__ ei) {
    int e = blockIdx.x * 256 + threadIdx.x;
    if (e < N_EDGES) atomicAdd(&g_deg[ei[N_EDGES + e]], 1);
}

__global__ void k_scan1() {
    __shared__ int sm[1024];
    int t = threadIdx.x;
    int i = blockIdx.x * 1024 + t;
    int v = (i < N_NODES) ? g_deg[i] : 0;
    sm[t] = v;
    __syncthreads();
    for (int off = 1; off < 1024; off <<= 1) {
        int tmp = (t >= off) ? sm[t - off] : 0;
        __syncthreads();
        sm[t] += tmp;
        __syncthreads();
    }
    if (i < N_NODES) g_rowptr[i] = sm[t] - v;   // exclusive within block
    if (t == 1023) g_bsums[blockIdx.x] = sm[1023];
}

__global__ void k_scan2(int nb) {
    if (threadIdx.x == 0) {
        int acc = 0;
        for (int b = 0; b < nb; b++) { int v = g_bsums[b]; g_bsums[b] = acc; acc += v; }
        g_rowptr[N_NODES] = acc;
    }
}

__global__ void k_scan3() {
    int i = blockIdx.x * 1024 + threadIdx.x;
    if (i < N_NODES) {
        int v = g_rowptr[i] + g_bsums[blockIdx.x];
        g_rowptr[i] = v;
        g_cursor[i] = v;
    }
}

__global__ void k_fill(const int* __restrict__ ei, const float* __restrict__ ew) {
    int e = blockIdx.x * 256 + threadIdx.x;
    if (e < N_EDGES) {
        int dst = ei[N_EDGES + e];
        int p = atomicAdd(&g_cursor[dst], 1);
        g_csr[p] = make_int2(ei[e], __float_as_int(ew[e]));
    }
}

// ---------------- aggregation with fused BN affine --------------------------
// t[node] = a (.) ( z[node] + sum_e w_e z[src_e] ) + c * (1 + sum_e w_e)
// (a,c) is the BN affine of the previous layer's z (identity for layer 1).
// For layer>=0 the input is device-global g_z (selected in device code).
__global__ void k_agg(const float* __restrict__ xin, int layer /* -1 = identity */,
                      const float* __restrict__ gam, const float* __restrict__ bet) {
    const float* __restrict__ zin = (layer < 0) ? xin : (const float*)g_z;
    int lane = threadIdx.x & 31;
    int node = (blockIdx.x * blockDim.x + threadIdx.x) >> 5;
    if (node >= N_NODES) return;

    float a0 = 1.0f, a1 = 1.0f, c0 = 0.0f, c1 = 0.0f;
    if (layer >= 0) {
        const float* st = &g_stats[layer * 128];
        const float inv = 1.0f / (float)N_NODES;
        float mu0 = st[lane] * inv, mu1 = st[lane + 32] * inv;
        float v0 = st[64 + lane] * inv - mu0 * mu0;
        float v1 = st[96 + lane] * inv - mu1 * mu1;
        a0 = rsqrtf(v0 + BN_EPS) * gam[lane];
        a1 = rsqrtf(v1 + BN_EPS) * gam[lane + 32];
        c0 = bet[lane] - mu0 * a0;
        c1 = bet[lane + 32] - mu1 * a1;
    }

    int beg = g_rowptr[node], end = g_rowptr[node + 1];
    float s0 = 0.0f, s1 = 0.0f, sw = 0.0f;
#pragma unroll 2
    for (int e = beg; e < end; ++e) {
        int2 cw = g_csr[e];
        float w = __int_as_float(cw.y);
        const float* r = zin + (size_t)cw.x * HID;
        s0 += w * r[lane];
        s1 += w * r[lane + 32];
        sw += w;
    }
    sw += 1.0f;
    size_t base = (size_t)node * HID;
    float z0 = zin[base + lane], z1 = zin[base + lane + 32];
    g_t[base + lane]      = a0 * (z0 + s0) + c0 * sw;
    g_t[base + lane + 32] = a1 * (z1 + s1) + c1 * sw;
}

// ---------------- tiled GEMM (64-node tile) + bias + relu + column stats ----
__global__ void k_gemm(const float* __restrict__ W, const float* __restrict__ bias,
                       int layer, int do_relu) {
    __shared__ float ts[64][68];      // [node][k], padded
    __shared__ float ws[64 * 64];     // W[k][col]
    int tid = threadIdx.x;
    int n0 = blockIdx.x * 64;

    for (int i = tid; i < 4096; i += 256) ws[i] = W[i];
#pragma unroll
    for (int it = 0; it < 4; ++it) {
        int li = it * 1024 + tid * 4;
        int node = li >> 6, k = li & 63;
        float4 v = make_float4(0.f, 0.f, 0.f, 0.f);
        if (n0 + node < N_NODES)
            v = *(const float4*)(g_t + (size_t)(n0 + node) * HID + k);
        *(float4*)&ts[node][k] = v;
    }
    __syncthreads();

    int tx = tid & 15, ty = tid >> 4;   // tx: 4-col group, ty: 4-node group
    float acc00=0,acc01=0,acc02=0,acc03=0, acc10=0,acc11=0,acc12=0,acc13=0;
    float acc20=0,acc21=0,acc22=0,acc23=0, acc30=0,acc31=0,acc32=0,acc33=0;
#pragma unroll
    for (int k = 0; k < 64; ++k) {
        float4 wv = *(const float4*)&ws[k * 64 + tx * 4];
        float a0 = ts[ty * 4 + 0][k];
        float a1 = ts[ty * 4 + 1][k];
        float a2 = ts[ty * 4 + 2][k];
        float a3 = ts[ty * 4 + 3][k];
        acc00 += a0*wv.x; acc01 += a0*wv.y; acc02 += a0*wv.z; acc03 += a0*wv.w;
        acc10 += a1*wv.x; acc11 += a1*wv.y; acc12 += a1*wv.z; acc13 += a1*wv.w;
        acc20 += a2*wv.x; acc21 += a2*wv.y; acc22 += a2*wv.z; acc23 += a2*wv.w;
        acc30 += a3*wv.x; acc31 += a3*wv.y; acc32 += a3*wv.z; acc33 += a3*wv.w;
    }

    float4 bv = *(const float4*)&bias[tx * 4];
    float sum0=0,sum1=0,sum2=0,sum3=0, sq0=0,sq1=0,sq2=0,sq3=0;
    float r0[4][4] = {{acc00,acc01,acc02,acc03},{acc10,acc11,acc12,acc13},
                      {acc20,acc21,acc22,acc23},{acc30,acc31,acc32,acc33}};
#pragma unroll
    for (int i = 0; i < 4; ++i) {
        int node = n0 + ty * 4 + i;
        float o0 = r0[i][0] + bv.x, o1 = r0[i][1] + bv.y;
        float o2 = r0[i][2] + bv.z, o3 = r0[i][3] + bv.w;
        if (do_relu) {
            o0 = fmaxf(o0, 0.f); o1 = fmaxf(o1, 0.f);
            o2 = fmaxf(o2, 0.f); o3 = fmaxf(o3, 0.f);
        }
        if (node < N_NODES) {
            float4 o = make_float4(o0, o1, o2, o3);
            *(float4*)(g_z + (size_t)node * HID + tx * 4) = o;
            sum0 += o0; sum1 += o1; sum2 += o2; sum3 += o3;
            sq0 += o0*o0; sq1 += o1*o1; sq2 += o2*o2; sq3 += o3*o3;
        }
    }

    // block-level stats reduction (reuse ts as scratch: need 2048 floats)
    __syncthreads();
    float* red = &ts[0][0];
    red[ty * 64 + tx * 4 + 0] = sum0;
    red[ty * 64 + tx * 4 + 1] = sum1;
    red[ty * 64 + tx * 4 + 2] = sum2;
    red[ty * 64 + tx * 4 + 3] = sum3;
    red[1024 + ty * 64 + tx * 4 + 0] = sq0;
    red[1024 + ty * 64 + tx * 4 + 1] = sq1;
    red[1024 + ty * 64 + tx * 4 + 2] = sq2;
    red[1024 + ty * 64 + tx * 4 + 3] = sq3;
    __syncthreads();
    if (tid < 128) {
        int which = tid >> 6, col = tid & 63;
        float S = 0.f;
#pragma unroll
        for (int t2 = 0; t2 < 16; ++t2) S += red[which * 1024 + t2 * 64 + col];
        atomicAdd(&g_stats[layer * 128 + which * 64 + col], S);
    }
}

// ---------------- layer-3 BN + segmented (sorted-batch) pooling -------------
__global__ void k_norm_pool(const float* __restrict__ gam, const float* __restrict__ bet,
                            const int* __restrict__ batch) {
    int col = threadIdx.x & 63;
    int run = blockIdx.x * (blockDim.x >> 6) + (threadIdx.x >> 6);
    int nruns = gridDim.x * (blockDim.x >> 6);
    int per = (N_NODES + nruns - 1) / nruns;
    int r0 = run * per;
    int r1 = min(N_NODES, r0 + per);

    const float* st = &g_stats[2 * 128];
    const float inv = 1.0f / (float)N_NODES;
    float mu = st[col] * inv;
    float var = st[64 + col] * inv - mu * mu;
    float sc = rsqrtf(var + BN_EPS) * gam[col];
    float bb = bet[col];

    int cur = -1;
    float acc = 0.0f;
    for (int n = r0; n < r1; ++n) {
        int gph = batch[n];
        float v = (g_z[(size_t)n * HID + col] - mu) * sc + bb;
        if (gph != cur) {
            if (cur >= 0) atomicAdd(&g_pooled[cur * HID + col], acc);
            cur = gph;
            acc = v;
        } else {
            acc += v;
        }
    }
    if (cur >= 0) atomicAdd(&g_pooled[cur * HID + col], acc);
}

// ---------------- final MLP: relu(pool) -> relu(@fcW1+b1) -> @fcW2+b2 -------
__global__ void k_final(const float* __restrict__ fcW1, const float* __restrict__ fcb1,
                        const float* __restrict__ fcW2, const float* __restrict__ fcb2,
                        float* __restrict__ out) {
    __shared__ float wsm[4096];
    __shared__ float b1s[64];
    __shared__ float w2s[64];
    __shared__ float psm[8][64];
    int tid = threadIdx.x;
    for (int i = tid; i < 4096; i += 256) wsm[i] = fcW1[i];
    if (tid < 64) { b1s[tid] = fcb1[tid]; w2s[tid] = fcW2[tid]; }
    __syncthreads();

    int lane = tid & 31, wid = tid >> 5;
    int gph = blockIdx.x * 8 + wid;
    float p0 = fmaxf(g_pooled[gph * HID + lane], 0.f);
    float p1 = fmaxf(g_pooled[gph * HID + lane + 32], 0.f);
    psm[wid][lane] = p0;
    psm[wid][lane + 32] = p1;
    __syncwarp();

    float h0 = b1s[lane], h1 = b1s[lane + 32];
#pragma unroll
    for (int k = 0; k < 64; ++k) {
        float pk = psm[wid][k];
        h0 += pk * wsm[k * 64 + lane];
        h1 += pk * wsm[k * 64 + lane + 32];
    }
    float part = fmaxf(h0, 0.f) * w2s[lane] + fmaxf(h1, 0.f) * w2s[lane + 32];
#pragma unroll
    for (int off = 16; off >= 1; off >>= 1)
        part += __shfl_xor_sync(0xffffffffu, part, off);
    if (lane == 0) out[gph] = part + fcb2[0];
}

// ---------------- host launcher ---------------------------------------------
extern "C" void kernel_launch(void* const* d_in, const int* in_sizes, int n_in,
                              void* d_out, int out_size) {
    const float* x     = (const float*)d_in[0];
    const int*   ei    = (const int*)d_in[1];     // int64 in reference -> int32 on device
    const float* ew    = (const float*)d_in[2];
    const int*   batch = (const int*)d_in[3];     // int64 in reference -> int32 on device
    const float *W1 = (const float*)d_in[4],  *b1 = (const float*)d_in[5];
    const float *W2 = (const float*)d_in[6],  *b2 = (const float*)d_in[7];
    const float *W3 = (const float*)d_in[8],  *b3 = (const float*)d_in[9];
    const float *fcW1 = (const float*)d_in[10], *fcb1 = (const float*)d_in[11];
    const float *fcW2 = (const float*)d_in[12], *fcb2 = (const float*)d_in[13];
    const float *g1 = (const float*)d_in[14], *be1 = (const float*)d_in[15];
    const float *g2 = (const float*)d_in[16], *be2 = (const float*)d_in[17];
    const float *g3 = (const float*)d_in[18], *be3 = (const float*)d_in[19];
    float* out = (float*)d_out;

    const int EB = (N_EDGES + 255) / 256;              // 3125
    const int NB1024 = (N_NODES + 1023) / 1024;        // 49
    const int AGG_B = (N_NODES * 32 + 255) / 256;      // 6250
    const int GEMM_B = (N_NODES + 63) / 64;            // 782

    k_init<<<(N_NODES + 255) / 256, 256>>>();
    k_count<<<EB, 256>>>(ei);
    k_scan1<<<NB1024, 1024>>>();
    k_scan2<<<1, 32>>>(NB1024);
    k_scan3<<<NB1024, 1024>>>();
    k_fill<<<EB, 256>>>(ei, ew);

    // layer 1 (identity affine; reads x)
    k_agg<<<AGG_B, 256>>>(x, -1, nullptr, nullptr);
    k_gemm<<<GEMM_B, 256>>>(W1, b1, 0, 1);
    // layer 2 (BN(relu z1) folded into aggregation; reads g_z internally)
    k_agg<<<AGG_B, 256>>>(nullptr, 0, g1, be1);
    k_gemm<<<GEMM_B, 256>>>(W2, b2, 1, 1);
    // layer 3
    k_agg<<<AGG_B, 256>>>(nullptr, 1, g2, be2);
    k_gemm<<<GEMM_B, 256>>>(W3, b3, 2, 0);
    // BN3 + global_add_pool (sorted batch, run-based)
    k_norm_pool<<<64, 256>>>(g3, be3, batch);
    // final MLP
    k_final<<<N_GRAPHS / 8, 256>>>(fcW1, fcb1, fcW2, fcb2, out);
}